// round 9
// baseline (speedup 1.0000x reference)
#include <cuda_runtime.h>
#include <cuda_fp16.h>
#include <math.h>

#define MAXN 100000
#define MAXE 1600000
#define HDIM 64
#define SCAN_B 1024

// Scratch (__device__ globals; no allocation allowed)
__device__ __align__(256) __half g_hsh[(size_t)MAXN * HDIM]; // (x@W)*dinv, fp16 for gather
__device__ __align__(256) float g_buf[(size_t)MAXN * HDIM];  // layer output / next input (fp32)
__device__ float g_dinv[MAXN];
__device__ int g_cnt[MAXN];        // in-degree histogram
__device__ int g_rowptr[MAXN + 1]; // CSR row offsets (by dst)
__device__ int g_cursor[MAXN];     // fill cursors
__device__ int g_csrc[MAXE];       // CSR src indices
__device__ int g_btotal[128];      // per-block totals (+1 sentinel) for decoupled scan

// packed f32x2 ops (B300)
#define FMA2(d, a, b, c) \
    asm("fma.rn.f32x2 %0, %1, %2, %3;" : "=l"(d) : "l"(a), "l"(b), "l"(c))
#define ADD2(d, a, b) \
    asm("add.rn.f32x2 %0, %1, %2;" : "=l"(d) : "l"(a), "l"(b))

// ---------------- CSR build ----------------
__global__ void hist_kernel(const int* __restrict__ dst, int E) {
    int i = blockIdx.x * blockDim.x + threadIdx.x;
    if (i < E) atomicAdd(&g_cnt[dst[i]], 1);
}

// Single-launch scan over g_cnt: block-local scan + decoupled lookback.
// Grid must be <= 128 blocks and fully wave-1 resident (98 blocks on 148 SMs).
__global__ __launch_bounds__(SCAN_B) void scan_fused_kernel(int n, int E) {
    __shared__ int wsum[32];
    __shared__ int s_prefix;
    int bid = blockIdx.x;
    int i = bid * SCAN_B + threadIdx.x;
    int lane = threadIdx.x & 31, w = threadIdx.x >> 5;
    int v = (i < n) ? g_cnt[i] : 0;
    int x = v;
#pragma unroll
    for (int off = 1; off < 32; off <<= 1) {
        int t = __shfl_up_sync(0xffffffffu, x, off);
        if (lane >= off) x += t;
    }
    if (lane == 31) wsum[w] = x;
    __syncthreads();
    if (w == 0) {
        int s = wsum[lane];
#pragma unroll
        for (int off = 1; off < 32; off <<= 1) {
            int t = __shfl_up_sync(0xffffffffu, s, off);
            if (lane >= off) s += t;
        }
        wsum[lane] = s;
    }
    __syncthreads();
    int incl = x + (w > 0 ? wsum[w - 1] : 0);

    if (threadIdx.x == 0) {
        s_prefix = 0;
        atomicExch(&g_btotal[bid], wsum[31] + 1);  // sentinel +1 (0 == not ready)
    }
    __syncthreads();
    if (threadIdx.x < bid) {
        int t;
        do { t = atomicAdd(&g_btotal[threadIdx.x], 0); } while (t == 0);
        atomicAdd_block(&s_prefix, t - 1);
    }
    __syncthreads();
    int prefix = s_prefix;

    if (i < n) {
        int r = prefix + incl - v;
        g_rowptr[i] = r;
        g_cursor[i] = r;
        g_dinv[i] = rsqrtf((float)v + 1.0f);
    }
    if (i == 0) g_rowptr[n] = E;
}

__global__ void fill_kernel(const int* __restrict__ src, const int* __restrict__ dst, int E) {
    int i = blockIdx.x * blockDim.x + threadIdx.x;
    if (i < E) {
        int pos = atomicAdd(&g_cursor[dst[i]], 1);
        g_csrc[pos] = src[i];
    }
}

// ---------------- GEMM: hs = half(X @ W * dinv) (packed f32x2 FMA) ----------------
template <int K>
__global__ __launch_bounds__(256) void gemm_kernel(const float* __restrict__ Xin,
                                                   const float* __restrict__ W, int n) {
    constexpr int KP = K + 4;
    extern __shared__ float smem[];
    float* sWt = smem;            // [64][KP] transposed W
    float* sX  = smem + 64 * KP;  // [64][K]

    const float* X = Xin ? Xin : g_buf;
    int tid = threadIdx.x;

    for (int i = tid; i < K * 64; i += 256) {
        int k = i >> 6, c = i & 63;
        sWt[c * KP + k] = W[i];
    }
    int row0 = blockIdx.x * 64;
    int nrows = n - row0; if (nrows > 64) nrows = 64;
    for (int i = tid; i < nrows * K; i += 256) sX[i] = X[(size_t)row0 * K + i];
    __syncthreads();

    int w = tid >> 5, lane = tid & 31;
    unsigned long long acc0[8], acc1[8];  // (even-k sum, odd-k sum) pairs
#pragma unroll
    for (int r = 0; r < 8; r++) { acc0[r] = 0ull; acc1[r] = 0ull; }

    const ulonglong2* wt0 = (const ulonglong2*)(sWt + lane * KP);
    const ulonglong2* wt1 = (const ulonglong2*)(sWt + (lane + 32) * KP);
#pragma unroll 4
    for (int k4 = 0; k4 < K / 4; k4++) {
        ulonglong2 w0 = wt0[k4];
        ulonglong2 w1 = wt1[k4];
#pragma unroll
        for (int r = 0; r < 8; r++) {
            ulonglong2 xv = ((const ulonglong2*)(sX + (w * 8 + r) * K))[k4];
            FMA2(acc0[r], w0.x, xv.x, acc0[r]);
            FMA2(acc0[r], w0.y, xv.y, acc0[r]);
            FMA2(acc1[r], w1.x, xv.x, acc1[r]);
            FMA2(acc1[r], w1.y, xv.y, acc1[r]);
        }
    }

#pragma unroll
    for (int r = 0; r < 8; r++) {
        int row = row0 + w * 8 + r;
        if (row < n) {
            float dv = g_dinv[row];
            float e0, o0, e1, o1;
            asm("mov.b64 {%0, %1}, %2;" : "=f"(e0), "=f"(o0) : "l"(acc0[r]));
            asm("mov.b64 {%0, %1}, %2;" : "=f"(e1), "=f"(o1) : "l"(acc1[r]));
            __half* hp = g_hsh + (size_t)row * HDIM;
            hp[lane]      = __float2half_rn((e0 + o0) * dv);
            hp[lane + 32] = __float2half_rn((e1 + o1) * dv);
        }
    }
}

// ---------------- fused aggregate + LN + GELU (+ head) ----------------
// warp per node; lane covers cols {2*lane, 2*lane+1}; fp16 gather, fp32 accumulate
__global__ __launch_bounds__(256) void agg_post_kernel(const float* __restrict__ b,
                                                       const float* __restrict__ g,
                                                       const float* __restrict__ be, int n, int last,
                                                       const float* __restrict__ Wh,
                                                       const float* __restrict__ bh,
                                                       float* __restrict__ out) {
    int w = threadIdx.x >> 5, lane = threadIdx.x & 31;
    int row = blockIdx.x * 8 + w;
    if (row >= n) return;

    const __half2* hs2 = (const __half2*)g_hsh;  // row stride = 32 half2
    size_t ro = (size_t)row * 32 + lane;

    float2 selfv = __half22float2(hs2[ro]);  // self-loop term (already dinv-scaled)
    unsigned long long aE, aO = 0ull;
    asm("mov.b64 %0, {%1, %2};" : "=l"(aE) : "f"(selfv.x), "f"(selfv.y));

    int beg = g_rowptr[row], end = g_rowptr[row + 1];
    for (int base = beg; base < end; base += 32) {
        int e = base + lane;
        int s = (e < end) ? g_csrc[e] : 0;
        int cnt = end - base; if (cnt > 32) cnt = 32;
        int j = 0;
        for (; j + 2 <= cnt; j += 2) {
            int s0 = __shfl_sync(0xffffffffu, s, j);
            int s1 = __shfl_sync(0xffffffffu, s, j + 1);
            float2 f0 = __half22float2(__ldg(hs2 + (size_t)s0 * 32 + lane));
            float2 f1 = __half22float2(__ldg(hs2 + (size_t)s1 * 32 + lane));
            unsigned long long p0, p1;
            asm("mov.b64 %0, {%1, %2};" : "=l"(p0) : "f"(f0.x), "f"(f0.y));
            asm("mov.b64 %0, {%1, %2};" : "=l"(p1) : "f"(f1.x), "f"(f1.y));
            ADD2(aE, aE, p0);
            ADD2(aO, aO, p1);
        }
        if (j < cnt) {
            int s0 = __shfl_sync(0xffffffffu, s, j);
            float2 f0 = __half22float2(__ldg(hs2 + (size_t)s0 * 32 + lane));
            unsigned long long p0;
            asm("mov.b64 %0, {%1, %2};" : "=l"(p0) : "f"(f0.x), "f"(f0.y));
            ADD2(aE, aE, p0);
        }
    }

    unsigned long long at;
    ADD2(at, aE, aO);
    float a0, a1;
    asm("mov.b64 {%0, %1}, %2;" : "=f"(a0), "=f"(a1) : "l"(at));

    float dv = g_dinv[row];
    float2 bb = ((const float2*)b)[lane];
    float v0 = a0 * dv + bb.x;
    float v1 = a1 * dv + bb.y;

    float s = v0 + v1;
#pragma unroll
    for (int off = 16; off; off >>= 1) s += __shfl_xor_sync(0xffffffffu, s, off);
    float m = s * (1.0f / 64.0f);
    float d0 = v0 - m, d1 = v1 - m;
    float vv = d0 * d0 + d1 * d1;
#pragma unroll
    for (int off = 16; off; off >>= 1) vv += __shfl_xor_sync(0xffffffffu, vv, off);
    float rs = rsqrtf(vv * (1.0f / 64.0f) + 1e-5f);

    float2 gg = ((const float2*)g)[lane];
    float2 ee = ((const float2*)be)[lane];
    float y0 = d0 * rs * gg.x + ee.x;
    float y1 = d1 * rs * gg.y + ee.y;
    y0 = 0.5f * y0 * (1.0f + erff(y0 * 0.70710678118654752f));
    y1 = 0.5f * y1 * (1.0f + erff(y1 * 0.70710678118654752f));

    if (!last) {
        float2 yy; yy.x = y0; yy.y = y1;
        ((float2*)g_buf)[ro] = yy;
    } else {
        float2 wh = ((const float2*)Wh)[lane];
        float hsum = y0 * wh.x + y1 * wh.y;
#pragma unroll
        for (int off = 16; off; off >>= 1) hsum += __shfl_xor_sync(0xffffffffu, hsum, off);
        if (lane == 0) out[row] = hsum + bh[0];
    }
}

extern "C" void kernel_launch(void* const* d_in, const int* in_sizes, int n_in,
                              void* d_out, int out_size) {
    const float* x   = (const float*)d_in[0];
    const int*   ei  = (const int*)d_in[1];
    const float* W1  = (const float*)d_in[2];
    const float* b1  = (const float*)d_in[3];
    const float* g1  = (const float*)d_in[4];
    const float* be1 = (const float*)d_in[5];
    const float* W2  = (const float*)d_in[6];
    const float* b2  = (const float*)d_in[7];
    const float* g2  = (const float*)d_in[8];
    const float* be2 = (const float*)d_in[9];
    const float* W3  = (const float*)d_in[10];
    const float* b3  = (const float*)d_in[11];
    const float* g3  = (const float*)d_in[12];
    const float* be3 = (const float*)d_in[13];
    const float* Wh  = (const float*)d_in[14];
    const float* bh  = (const float*)d_in[15];
    float* out = (float*)d_out;

    int N = in_sizes[0] / 128;
    int E = in_sizes[1] / 2;
    const int* src = ei;
    const int* dst = ei + E;

    size_t sh128 = (size_t)64 * (132 + 128) * sizeof(float);
    size_t sh64  = (size_t)64 * (68 + 64) * sizeof(float);
    cudaFuncSetAttribute(gemm_kernel<128>, cudaFuncAttributeMaxDynamicSharedMemorySize, (int)sh128);
    cudaFuncSetAttribute(gemm_kernel<64>,  cudaFuncAttributeMaxDynamicSharedMemorySize, (int)sh64);

    int nscan = (N + SCAN_B - 1) / SCAN_B;  // 98 <= 128, fully wave-1 resident
    int gblocks = (N + 63) / 64;
    int ablocks = (N + 7) / 8;

    // CSR build (once, reused by all 3 layers) + dinv
    void* cnt_ptr = nullptr; void* btot_ptr = nullptr;
    cudaGetSymbolAddress(&cnt_ptr, g_cnt);
    cudaGetSymbolAddress(&btot_ptr, g_btotal);
    cudaMemsetAsync(cnt_ptr, 0, (size_t)N * sizeof(int));
    cudaMemsetAsync(btot_ptr, 0, 128 * sizeof(int));
    hist_kernel<<<(E + 255) / 256, 256>>>(dst, E);
    scan_fused_kernel<<<nscan, SCAN_B>>>(N, E);
    fill_kernel<<<(E + 255) / 256, 256>>>(src, dst, E);

    // layer 1 (K=128)
    gemm_kernel<128><<<gblocks, 256, sh128>>>(x, W1, N);
    agg_post_kernel<<<ablocks, 256>>>(b1, g1, be1, N, 0, nullptr, nullptr, nullptr);

    // layer 2 (K=64)
    gemm_kernel<64><<<gblocks, 256, sh64>>>(nullptr, W2, N);
    agg_post_kernel<<<ablocks, 256>>>(b2, g2, be2, N, 0, nullptr, nullptr, nullptr);

    // layer 3 (K=64) + fused head
    gemm_kernel<64><<<gblocks, 256, sh64>>>(nullptr, W3, N);
    agg_post_kernel<<<ablocks, 256>>>(b3, g3, be3, N, 1, Wh, bh, out);
}